// round 1
// baseline (speedup 1.0000x reference)
#include <cuda_runtime.h>
#include <cuda_bf16.h>

// Problem dims
#define B    32
#define CIN  32
#define COUT 64
#define HH   128
#define WW   128
#define KH   3
#define KW   3
#define MAXCN 64
#define HO   126
#define WO   126

// Effective dense kernel scratch: [COUT][CIN][9]
__device__ float g_kd[COUT * CIN * 9];

// ---------------------------------------------------------------------------
// Kernel 1: fold padded kernel bank into dense [O, C, 3, 3]
// kd[o][c] = (c < cn[o] ? w[o][c] : 0) + (c+32 < cn[o] ? w[o][c+32] : 0)
// ---------------------------------------------------------------------------
__global__ void build_kdense(const float* __restrict__ w,
                             const int* __restrict__ cn) {
    int o = blockIdx.x;            // 0..63
    int t = threadIdx.x;           // 0..287  (c*9 + k)
    if (t < CIN * 9) {
        int c = t / 9;
        int k = t % 9;
        int cnum = cn[o];
        float v = 0.f;
        if (c < cnum)        v += w[(o * MAXCN + c) * 9 + k];
        if (c + CIN < cnum)  v += w[(o * MAXCN + c + CIN) * 9 + k];
        g_kd[o * (CIN * 9) + t] = v;
    }
}

// ---------------------------------------------------------------------------
// Kernel 2: direct conv, register-blocked.
// Block: 256 threads. Tile: 32 rows x 64 cols of output, 8 output channels.
// Thread (ty = tid/8 in 0..31, tx = tid%8): row ty, columns tx*8..tx*8+7.
// Accumulators: 8 oc x 8 pix = 64 regs. Sliding 10-wide x window per (c,kh).
// ---------------------------------------------------------------------------
#define TH 32
#define TW 64
#define OCG 8          // output channels per block
#define XT_H (TH + 2)  // 34
#define XT_W (TW + 2)  // 66

__global__ __launch_bounds__(256)
void conv_kernel(const float* __restrict__ x,
                 const float* __restrict__ bias,
                 float* __restrict__ out) {
    __shared__ float xs[XT_H][XT_W];            // 34*66*4 = 8976 B
    __shared__ float ws[OCG][CIN][9];           // 8*32*9*4 = 9216 B

    const int tid = threadIdx.x;
    const int ty  = tid >> 3;                   // 0..31
    const int tx8 = (tid & 7) * 8;              // 0,8,..,56

    const int tilew = blockIdx.x & 1;           // 2 tiles of 64 cover 126
    const int tileh = blockIdx.x >> 1;          // 4 tiles of 32 cover 126
    const int og    = blockIdx.y;               // 0..7
    const int b     = blockIdx.z;               // 0..31

    const int h0 = tileh * TH;
    const int w0 = tilew * TW;

    // Load this block's weights once: 8 oc * 288 = 2304 floats
    for (int i = tid; i < OCG * CIN * 9; i += 256) {
        int o = i / (CIN * 9);
        int r = i % (CIN * 9);
        ws[o][0][r] = g_kd[(og * OCG + o) * (CIN * 9) + r];
    }

    float acc[OCG][8];
    #pragma unroll
    for (int o = 0; o < OCG; ++o)
        #pragma unroll
        for (int p = 0; p < 8; ++p) acc[o][p] = 0.f;

    const float* xb = x + (size_t)b * CIN * HH * WW;

    for (int c = 0; c < CIN; ++c) {
        __syncthreads();
        // Load input tile (34 x 66) for channel c, clamped at image edge
        const float* xc = xb + (size_t)c * HH * WW;
        #pragma unroll
        for (int i = tid; i < XT_H * XT_W; i += 256) {
            int r   = i / XT_W;
            int col = i % XT_W;
            int gr = h0 + r;
            int gc = w0 + col;
            float v = (gr < HH && gc < WW) ? xc[gr * WW + gc] : 0.f;
            xs[r][col] = v;
        }
        __syncthreads();

        #pragma unroll
        for (int kh = 0; kh < 3; ++kh) {
            float xv[10];
            #pragma unroll
            for (int i = 0; i < 10; ++i)
                xv[i] = xs[ty + kh][tx8 + i];
            #pragma unroll
            for (int kw = 0; kw < 3; ++kw) {
                #pragma unroll
                for (int o = 0; o < OCG; ++o) {
                    float wv = ws[o][c][kh * 3 + kw];
                    #pragma unroll
                    for (int p = 0; p < 8; ++p)
                        acc[o][p] += wv * xv[kw + p];
                }
            }
        }
    }

    // Store with bias, bounds-checked (126 not divisible by tile dims)
    const int ho = h0 + ty;
    if (ho < HO) {
        #pragma unroll
        for (int o = 0; o < OCG; ++o) {
            const int oc = og * OCG + o;
            float*       op = out  + ((size_t)(b * COUT + oc) * HO + ho) * WO;
            const float* bp = bias + ((size_t)oc * HO + ho) * WO;
            #pragma unroll
            for (int p = 0; p < 8; ++p) {
                int wo = w0 + tx8 + p;
                if (wo < WO) op[wo] = acc[o][p] + bp[wo];
            }
        }
    }
}

// ---------------------------------------------------------------------------
extern "C" void kernel_launch(void* const* d_in, const int* in_sizes, int n_in,
                              void* d_out, int out_size) {
    const float* x       = (const float*)d_in[0];  // [32,32,128,128]
    const float* weights = (const float*)d_in[1];  // [64,64,3,3]
    const float* bias    = (const float*)d_in[2];  // [64,126,126]
    const int*   cn      = (const int*)d_in[3];    // [64]
    float* out = (float*)d_out;                    // [32,64,126,126]

    build_kdense<<<COUT, CIN * 9>>>(weights, cn);

    dim3 grid(8 /* 2w x 4h tiles */, COUT / OCG, B);
    conv_kernel<<<grid, 256>>>(x, bias, out);
}

// round 3
// speedup vs baseline: 1.3473x; 1.3473x over previous
#include <cuda_runtime.h>
#include <cuda_bf16.h>

// Problem dims
#define B    32
#define CIN  32
#define COUT 64
#define HH   128
#define WW   128
#define MAXCN 64
#define HO   126
#define WO   126

// Effective dense kernel scratch: [COUT][CIN][9]
__device__ float g_kd[COUT * CIN * 9];

// ---------------------------------------------------------------------------
// Kernel 1: fold padded kernel bank into dense [O, C, 3, 3]
// ---------------------------------------------------------------------------
__global__ void build_kdense(const float* __restrict__ w,
                             const int* __restrict__ cn) {
    int o = blockIdx.x;            // 0..63
    int t = threadIdx.x;           // 0..287  (c*9 + k)
    if (t < CIN * 9) {
        int c = t / 9;
        int k = t % 9;
        int cnum = cn[o];
        float v = 0.f;
        if (c < cnum)        v += w[(o * MAXCN + c) * 9 + k];
        if (c + CIN < cnum)  v += w[(o * MAXCN + c + CIN) * 9 + k];
        g_kd[o * (CIN * 9) + t] = v;
    }
}

// ---------------------------------------------------------------------------
// Packed f32x2 helpers (Blackwell FFMA2 path)
// ---------------------------------------------------------------------------
__device__ __forceinline__ void ffma2(unsigned long long& d,
                                      unsigned long long a,
                                      unsigned long long b) {
    asm("fma.rn.f32x2 %0, %1, %2, %0;" : "+l"(d) : "l"(a), "l"(b));
}
__device__ __forceinline__ unsigned long long pack2(float x, float y) {
    unsigned long long r;
    asm("mov.b64 %0, {%1, %2};" : "=l"(r) : "f"(x), "f"(y));
    return r;
}
__device__ __forceinline__ float2 unpack2(unsigned long long v) {
    float2 f;
    asm("mov.b64 {%0, %1}, %2;" : "=f"(f.x), "=f"(f.y) : "l"(v));
    return f;
}

// ---------------------------------------------------------------------------
// Kernel 2: direct conv, FFMA2 register-blocked, double-buffered x tile.
// Block: 256 threads. Tile: 32 rows x 64 cols of output, 8 output channels
// (4 packed channel-pairs). Thread: row ty=tid/8, cols tx8=(tid%8)*8..+7.
// ---------------------------------------------------------------------------
#define TH 32
#define TW 64
#define OCG 8
#define XT_H 34
#define XT_W 68          // padded from 66 -> rows 16B aligned for LDS.128
#define XT_N (XT_H * XT_W)   // 2312
#define LDS_PT 10        // ceil(2312/256)

__global__ __launch_bounds__(256)
void conv_kernel(const float* __restrict__ x,
                 const float* __restrict__ bias,
                 float* __restrict__ out) {
    __shared__ float  xs[2][XT_N];         // 2 * 9248 B
    __shared__ float2 ws2[CIN][9][OCG/2];  // 9216 B  (channel-pairs packed)

    const int tid = threadIdx.x;
    const int ty  = tid >> 3;                   // 0..31
    const int tx8 = (tid & 7) * 8;              // 0..56

    const int tilew = blockIdx.x & 1;
    const int tileh = blockIdx.x >> 1;
    const int og    = blockIdx.y;               // 0..7
    const int b     = blockIdx.z;

    const int h0 = tileh * TH;
    const int w0 = tilew * TW;

    // Pack this block's weights as channel-pairs: ws2[c][k][j] = (kd[2j], kd[2j+1])
    for (int i = tid; i < CIN * 9 * (OCG / 2); i += 256) {
        int c = i / 36;
        int k = (i % 36) >> 2;
        int j = i & 3;
        int oc0 = og * OCG + 2 * j;
        ws2[c][k][j] = make_float2(g_kd[oc0 * (CIN * 9) + c * 9 + k],
                                   g_kd[(oc0 + 1) * (CIN * 9) + c * 9 + k]);
    }

    // Precompute tile-load gather offsets (constant across channels)
    int  goff[LDS_PT];    // global offset within channel plane, or -1 (load 0)
    int  soff[LDS_PT];    // smem offset
    bool svalid[LDS_PT];  // whether this slot stores at all
    #pragma unroll
    for (int k = 0; k < LDS_PT; ++k) {
        int i = tid + k * 256;
        svalid[k] = (i < XT_N);
        if (svalid[k]) {
            int r   = i / XT_W;
            int col = i % XT_W;
            int gr = h0 + r;
            int gc = w0 + col;
            goff[k] = (gr < HH && gc < WW && col < 66) ? gr * WW + gc : -1;
            soff[k] = i;
        } else {
            goff[k] = -1;
            soff[k] = 0;
        }
    }

    unsigned long long accp[OCG / 2][8];
    #pragma unroll
    for (int j = 0; j < OCG / 2; ++j)
        #pragma unroll
        for (int p = 0; p < 8; ++p) accp[j][p] = 0ull;

    const float* xb = x + (size_t)b * CIN * HH * WW;

    // Prologue: load channel 0 tile into buffer 0
    {
        const float* xc = xb;
        float ld[LDS_PT];
        #pragma unroll
        for (int k = 0; k < LDS_PT; ++k)
            ld[k] = (goff[k] >= 0) ? __ldg(xc + goff[k]) : 0.f;
        #pragma unroll
        for (int k = 0; k < LDS_PT; ++k)
            if (svalid[k]) xs[0][soff[k]] = ld[k];
    }
    __syncthreads();

    for (int c = 0; c < CIN; ++c) {
        const int cur = c & 1;

        // Prefetch next channel tile into the other buffer
        if (c + 1 < CIN) {
            const float* xc = xb + (size_t)(c + 1) * HH * WW;
            float ld[LDS_PT];
            #pragma unroll
            for (int k = 0; k < LDS_PT; ++k)
                ld[k] = (goff[k] >= 0) ? __ldg(xc + goff[k]) : 0.f;
            #pragma unroll
            for (int k = 0; k < LDS_PT; ++k)
                if (svalid[k]) xs[cur ^ 1][soff[k]] = ld[k];
        }

        // Compute from current buffer
        const float* xsb = xs[cur];
        #pragma unroll
        for (int kh = 0; kh < 3; ++kh) {
            const float* row = xsb + (ty + kh) * XT_W + tx8;
            float4 a  = *(const float4*)(row);
            float4 b4 = *(const float4*)(row + 4);
            float  x8 = row[8];
            float  x9 = row[9];
            unsigned long long xx[10];
            xx[0] = pack2(a.x, a.x);  xx[1] = pack2(a.y, a.y);
            xx[2] = pack2(a.z, a.z);  xx[3] = pack2(a.w, a.w);
            xx[4] = pack2(b4.x, b4.x); xx[5] = pack2(b4.y, b4.y);
            xx[6] = pack2(b4.z, b4.z); xx[7] = pack2(b4.w, b4.w);
            xx[8] = pack2(x8, x8);    xx[9] = pack2(x9, x9);

            #pragma unroll
            for (int kw = 0; kw < 3; ++kw) {
                #pragma unroll
                for (int j = 0; j < OCG / 2; ++j) {
                    unsigned long long wv =
                        *reinterpret_cast<const unsigned long long*>(
                            &ws2[c][kh * 3 + kw][j]);
                    #pragma unroll
                    for (int p = 0; p < 8; ++p)
                        ffma2(accp[j][p], wv, xx[kw + p]);
                }
            }
        }
        __syncthreads();
    }

    // Epilogue: unpack, add bias, store (bounds-checked: 126 edges)
    const int ho = h0 + ty;
    if (ho < HO) {
        #pragma unroll
        for (int j = 0; j < OCG / 2; ++j) {
            const int oc0 = og * OCG + 2 * j;
            float*       op0 = out  + ((size_t)(b * COUT + oc0) * HO + ho) * WO;
            float*       op1 = op0 + (size_t)HO * WO;
            const float* bp0 = bias + ((size_t)oc0 * HO + ho) * WO;
            const float* bp1 = bp0 + (size_t)HO * WO;
            #pragma unroll
            for (int p = 0; p < 8; ++p) {
                int wo = w0 + tx8 + p;
                if (wo < WO) {
                    float2 v = unpack2(accp[j][p]);
                    op0[wo] = v.x + bp0[wo];
                    op1[wo] = v.y + bp1[wo];
                }
            }
        }
    }
}

// ---------------------------------------------------------------------------
extern "C" void kernel_launch(void* const* d_in, const int* in_sizes, int n_in,
                              void* d_out, int out_size) {
    const float* x       = (const float*)d_in[0];  // [32,32,128,128]
    const float* weights = (const float*)d_in[1];  // [64,64,3,3]
    const float* bias    = (const float*)d_in[2];  // [64,126,126]
    const int*   cn      = (const int*)d_in[3];    // [64]
    float* out = (float*)d_out;                    // [32,64,126,126]

    build_kdense<<<COUT, CIN * 9>>>(weights, cn);

    dim3 grid(8 /* 2w x 4h */, COUT / OCG, B);
    conv_kernel<<<grid, 256>>>(x, bias, out);
}

// round 5
// speedup vs baseline: 1.3653x; 1.0133x over previous
#include <cuda_runtime.h>
#include <cuda_bf16.h>

// Problem dims
#define B    32
#define CIN  32
#define COUT 64
#define HH   128
#define WW   128
#define MAXCN 64
#define HO   126
#define WO   126

// Effective dense kernel scratch: [COUT][CIN][9]
__device__ float g_kd[COUT * CIN * 9];

// ---------------------------------------------------------------------------
// Kernel 1: fold padded kernel bank into dense [O, C, 3, 3]
// ---------------------------------------------------------------------------
__global__ void build_kdense(const float* __restrict__ w,
                             const int* __restrict__ cn) {
    int o = blockIdx.x;
    int t = threadIdx.x;
    if (t < CIN * 9) {
        int c = t / 9;
        int k = t % 9;
        int cnum = cn[o];
        float v = 0.f;
        if (c < cnum)        v += w[(o * MAXCN + c) * 9 + k];
        if (c + CIN < cnum)  v += w[(o * MAXCN + c + CIN) * 9 + k];
        g_kd[o * (CIN * 9) + t] = v;
    }
}

// ---------------------------------------------------------------------------
// Packed f32x2 helpers (Blackwell FFMA2 path)
// ---------------------------------------------------------------------------
__device__ __forceinline__ void ffma2(unsigned long long& d,
                                      unsigned long long a,
                                      unsigned long long b) {
    asm("fma.rn.f32x2 %0, %1, %2, %0;" : "+l"(d) : "l"(a), "l"(b));
}
__device__ __forceinline__ unsigned long long pack2(float x, float y) {
    unsigned long long r;
    asm("mov.b64 %0, {%1, %2};" : "=l"(r) : "f"(x), "f"(y));
    return r;
}
__device__ __forceinline__ float2 unpack2(unsigned long long v) {
    float2 f;
    asm("mov.b64 {%0, %1}, %2;" : "=f"(f.x), "=f"(f.y) : "l"(v));
    return f;
}

// ---------------------------------------------------------------------------
// Kernel 2: direct conv, FFMA2, double-buffered with latency-hiding order:
//   LDG(next) -> compute(cur) -> STS(next) -> barrier
// ---------------------------------------------------------------------------
#define TH 32
#define TW 64
#define OCG 8
#define XT_H 34
#define XT_W 68
#define XT_N (XT_H * XT_W)   // 2312
#define LDS_PT 10            // ceil(2312/256)

__global__ __launch_bounds__(256)
void conv_kernel(const float* __restrict__ x,
                 const float* __restrict__ bias,
                 float* __restrict__ out) {
    __shared__ float  xs[2][XT_N];
    __shared__ float2 ws2[CIN][9][OCG/2];

    const int tid = threadIdx.x;
    const int ty  = tid >> 3;
    const int tx8 = (tid & 7) * 8;

    const int tilew = blockIdx.x & 1;
    const int tileh = blockIdx.x >> 1;
    const int og    = blockIdx.y;
    const int b     = blockIdx.z;

    const int h0 = tileh * TH;
    const int w0 = tilew * TW;

    // Pack weights as channel-pairs
    for (int i = tid; i < CIN * 9 * (OCG / 2); i += 256) {
        int c = i / 36;
        int k = (i % 36) >> 2;
        int j = i & 3;
        int oc0 = og * OCG + 2 * j;
        ws2[c][k][j] = make_float2(g_kd[oc0 * (CIN * 9) + c * 9 + k],
                                   g_kd[(oc0 + 1) * (CIN * 9) + c * 9 + k]);
    }

    // Precompute gather offsets (constant across channels)
    int  goff[LDS_PT];
    int  soff[LDS_PT];
    bool svalid[LDS_PT];
    #pragma unroll
    for (int k = 0; k < LDS_PT; ++k) {
        int i = tid + k * 256;
        svalid[k] = (i < XT_N);
        if (svalid[k]) {
            int r   = i / XT_W;
            int col = i % XT_W;
            int gr = h0 + r;
            int gc = w0 + col;
            goff[k] = (gr < HH && gc < WW && col < 66) ? gr * WW + gc : -1;
            soff[k] = i;
        } else {
            goff[k] = -1;
            soff[k] = 0;
        }
    }

    unsigned long long accp[OCG / 2][8];
    #pragma unroll
    for (int j = 0; j < OCG / 2; ++j)
        #pragma unroll
        for (int p = 0; p < 8; ++p) accp[j][p] = 0ull;

    const float* xb = x + (size_t)b * CIN * HH * WW;

    // Prologue: channel 0 into buffer 0
    {
        float ld[LDS_PT];
        #pragma unroll
        for (int k = 0; k < LDS_PT; ++k)
            ld[k] = (goff[k] >= 0) ? __ldg(xb + goff[k]) : 0.f;
        #pragma unroll
        for (int k = 0; k < LDS_PT; ++k)
            if (svalid[k]) xs[0][soff[k]] = ld[k];
    }
    __syncthreads();

    #pragma unroll 2
    for (int c = 0; c < CIN; ++c) {
        const int cur = c & 1;

        // Issue next-channel loads EARLY (results consumed after compute)
        float ld[LDS_PT];
        if (c + 1 < CIN) {
            const float* xc = xb + (size_t)(c + 1) * HH * WW;
            #pragma unroll
            for (int k = 0; k < LDS_PT; ++k)
                ld[k] = (goff[k] >= 0) ? __ldg(xc + goff[k]) : 0.f;
        }

        // Compute from current buffer — hides the LDG latency
        const float* xsb = xs[cur];
        #pragma unroll
        for (int kh = 0; kh < 3; ++kh) {
            const float* row = xsb + (ty + kh) * XT_W + tx8;
            float4 a  = *(const float4*)(row);
            float4 b4 = *(const float4*)(row + 4);
            float  x8 = row[8];
            float  x9 = row[9];
            unsigned long long xx[10];
            xx[0] = pack2(a.x, a.x);   xx[1] = pack2(a.y, a.y);
            xx[2] = pack2(a.z, a.z);   xx[3] = pack2(a.w, a.w);
            xx[4] = pack2(b4.x, b4.x); xx[5] = pack2(b4.y, b4.y);
            xx[6] = pack2(b4.z, b4.z); xx[7] = pack2(b4.w, b4.w);
            xx[8] = pack2(x8, x8);     xx[9] = pack2(x9, x9);

            #pragma unroll
            for (int kw = 0; kw < 3; ++kw) {
                #pragma unroll
                for (int j = 0; j < OCG / 2; ++j) {
                    unsigned long long wv =
                        *reinterpret_cast<const unsigned long long*>(
                            &ws2[c][kh * 3 + kw][j]);
                    #pragma unroll
                    for (int p = 0; p < 8; ++p)
                        ffma2(accp[j][p], wv, xx[kw + p]);
                }
            }
        }

        // Now commit next tile to the other buffer and sync once
        if (c + 1 < CIN) {
            #pragma unroll
            for (int k = 0; k < LDS_PT; ++k)
                if (svalid[k]) xs[cur ^ 1][soff[k]] = ld[k];
        }
        __syncthreads();
    }

    // Epilogue: unpack, add bias, store
    const int ho = h0 + ty;
    if (ho < HO) {
        #pragma unroll
        for (int j = 0; j < OCG / 2; ++j) {
            const int oc0 = og * OCG + 2 * j;
            float*       op0 = out  + ((size_t)(b * COUT + oc0) * HO + ho) * WO;
            float*       op1 = op0 + (size_t)HO * WO;
            const float* bp0 = bias + ((size_t)oc0 * HO + ho) * WO;
            const float* bp1 = bp0 + (size_t)HO * WO;
            #pragma unroll
            for (int p = 0; p < 8; ++p) {
                int wo = w0 + tx8 + p;
                if (wo < WO) {
                    float2 v = unpack2(accp[j][p]);
                    op0[wo] = v.x + bp0[wo];
                    op1[wo] = v.y + bp1[wo];
                }
            }
        }
    }
}

// ---------------------------------------------------------------------------
extern "C" void kernel_launch(void* const* d_in, const int* in_sizes, int n_in,
                              void* d_out, int out_size) {
    const float* x       = (const float*)d_in[0];
    const float* weights = (const float*)d_in[1];
    const float* bias    = (const float*)d_in[2];
    const int*   cn      = (const int*)d_in[3];
    float* out = (float*)d_out;

    build_kdense<<<COUT, CIN * 9>>>(weights, cn);

    dim3 grid(8, COUT / OCG, B);
    conv_kernel<<<grid, 256>>>(x, bias, out);
}

// round 6
// speedup vs baseline: 1.5124x; 1.1077x over previous
#include <cuda_runtime.h>
#include <cuda_bf16.h>
#include <cstdint>

// Problem dims
#define B    32
#define CIN  32
#define COUT 64
#define HH   128
#define WW   128
#define MAXCN 64
#define HO   126
#define WO   126

// Effective dense kernel scratch: [COUT][CIN][9]
__device__ float g_kd[COUT * CIN * 9];

// ---------------------------------------------------------------------------
// Kernel 1: fold padded kernel bank into dense [O, C, 3, 3]
// ---------------------------------------------------------------------------
__global__ void build_kdense(const float* __restrict__ w,
                             const int* __restrict__ cn) {
    int o = blockIdx.x;
    int t = threadIdx.x;
    if (t < CIN * 9) {
        int c = t / 9;
        int k = t % 9;
        int cnum = cn[o];
        float v = 0.f;
        if (c < cnum)        v += w[(o * MAXCN + c) * 9 + k];
        if (c + CIN < cnum)  v += w[(o * MAXCN + c + CIN) * 9 + k];
        g_kd[o * (CIN * 9) + t] = v;
    }
}

// ---------------------------------------------------------------------------
// Packed f32x2 + cp.async helpers
// ---------------------------------------------------------------------------
__device__ __forceinline__ void ffma2(unsigned long long& d,
                                      unsigned long long a,
                                      unsigned long long b) {
    asm("fma.rn.f32x2 %0, %1, %2, %0;" : "+l"(d) : "l"(a), "l"(b));
}
__device__ __forceinline__ unsigned long long pack2(float x, float y) {
    unsigned long long r;
    asm("mov.b64 %0, {%1, %2};" : "=l"(r) : "f"(x), "f"(y));
    return r;
}
__device__ __forceinline__ float2 unpack2(unsigned long long v) {
    float2 f;
    asm("mov.b64 {%0, %1}, %2;" : "=f"(f.x), "=f"(f.y) : "l"(v));
    return f;
}
// Predicated 4-byte async copy: fires only when goff >= 0.
__device__ __forceinline__ void cp_async4(uint32_t saddr, const float* gptr,
                                          int goff) {
    asm volatile(
        "{\n\t"
        ".reg .pred p;\n\t"
        "setp.ge.s32 p, %2, 0;\n\t"
        "@p cp.async.ca.shared.global [%0], [%1], 4;\n\t"
        "}" :: "r"(saddr), "l"(gptr), "r"(goff));
}
__device__ __forceinline__ void cp_commit() {
    asm volatile("cp.async.commit_group;");
}
__device__ __forceinline__ void cp_wait_all() {
    asm volatile("cp.async.wait_group 0;");
}

// ---------------------------------------------------------------------------
// Kernel 2: direct conv, FFMA2, cp.async double-buffered pipeline:
//   cp.async(next) -> compute(cur) -> wait -> barrier
// ---------------------------------------------------------------------------
#define TH 32
#define TW 64
#define OCG 8
#define XT_H 34
#define XT_W 68
#define XT_N (XT_H * XT_W)   // 2312
#define LDS_PT 10            // ceil(2312/256)

__global__ __launch_bounds__(256, 2)
void conv_kernel(const float* __restrict__ x,
                 const float* __restrict__ bias,
                 float* __restrict__ out) {
    __shared__ float  xs[2][XT_N];
    __shared__ float2 ws2[CIN][9][OCG/2];

    const int tid = threadIdx.x;
    const int ty  = tid >> 3;
    const int tx8 = (tid & 7) * 8;

    const int tilew = blockIdx.x & 1;
    const int tileh = blockIdx.x >> 1;
    const int og    = blockIdx.y;
    const int b     = blockIdx.z;

    const int h0 = tileh * TH;
    const int w0 = tilew * TW;

    // Pack weights as channel-pairs
    for (int i = tid; i < CIN * 9 * (OCG / 2); i += 256) {
        int c = i / 36;
        int k = (i % 36) >> 2;
        int j = i & 3;
        int oc0 = og * OCG + 2 * j;
        ws2[c][k][j] = make_float2(g_kd[oc0 * (CIN * 9) + c * 9 + k],
                                   g_kd[(oc0 + 1) * (CIN * 9) + c * 9 + k]);
    }

    // Precompute gather offsets (constant across channels).
    // goff >= 0: valid copy. goff < 0: either zero-halo (pre-zeroed once) or
    // tail slot (no store at all).
    int      goff[LDS_PT];
    uint32_t sa0[LDS_PT];     // smem byte address in buffer 0
    #pragma unroll
    for (int k = 0; k < LDS_PT; ++k) {
        int i = tid + k * 256;
        bool sv = (i < XT_N);
        int r   = i / XT_W;
        int col = i % XT_W;
        int gr = h0 + r;
        int gc = w0 + col;
        bool gv = sv && (gr < HH) && (gc < WW) && (col < 66);
        goff[k] = gv ? (gr * WW + gc) : -1;
        sa0[k]  = (uint32_t)__cvta_generic_to_shared(&xs[0][sv ? i : 0]);
        // Zero-fill invalid-but-stored halo slots ONCE (both buffers)
        if (sv && !gv) { xs[0][i] = 0.f; xs[1][i] = 0.f; }
    }

    unsigned long long accp[OCG / 2][8];
    #pragma unroll
    for (int j = 0; j < OCG / 2; ++j)
        #pragma unroll
        for (int p = 0; p < 8; ++p) accp[j][p] = 0ull;

    const float* xb = x + (size_t)b * CIN * HH * WW;
    const uint32_t BUF_STRIDE = XT_N * 4;

    // Prologue: channel 0 into buffer 0
    #pragma unroll
    for (int k = 0; k < LDS_PT; ++k)
        cp_async4(sa0[k], xb + goff[k], goff[k]);
    cp_commit();
    cp_wait_all();
    __syncthreads();

    #pragma unroll 2
    for (int c = 0; c < CIN; ++c) {
        const int cur = c & 1;

        // Kick off next channel's copy into the other buffer
        if (c + 1 < CIN) {
            const float* xc = xb + (size_t)(c + 1) * HH * WW;
            const uint32_t off = (cur ^ 1) ? BUF_STRIDE : 0u;
            #pragma unroll
            for (int k = 0; k < LDS_PT; ++k)
                cp_async4(sa0[k] + off, xc + goff[k], goff[k]);
            cp_commit();
        }

        // Compute from current buffer (overlaps the async copy)
        const float* xsb = xs[cur];
        #pragma unroll
        for (int kh = 0; kh < 3; ++kh) {
            const float* row = xsb + (ty + kh) * XT_W + tx8;
            float4 a  = *(const float4*)(row);
            float4 b4 = *(const float4*)(row + 4);
            float  x8 = row[8];
            float  x9 = row[9];
            unsigned long long xx[10];
            xx[0] = pack2(a.x, a.x);   xx[1] = pack2(a.y, a.y);
            xx[2] = pack2(a.z, a.z);   xx[3] = pack2(a.w, a.w);
            xx[4] = pack2(b4.x, b4.x); xx[5] = pack2(b4.y, b4.y);
            xx[6] = pack2(b4.z, b4.z); xx[7] = pack2(b4.w, b4.w);
            xx[8] = pack2(x8, x8);     xx[9] = pack2(x9, x9);

            #pragma unroll
            for (int kw = 0; kw < 3; ++kw) {
                #pragma unroll
                for (int j = 0; j < OCG / 2; ++j) {
                    unsigned long long wv =
                        *reinterpret_cast<const unsigned long long*>(
                            &ws2[c][kh * 3 + kw][j]);
                    #pragma unroll
                    for (int p = 0; p < 8; ++p)
                        ffma2(accp[j][p], wv, xx[kw + p]);
                }
            }
        }

        cp_wait_all();
        __syncthreads();
    }

    // Epilogue: unpack, add bias, store
    const int ho = h0 + ty;
    if (ho < HO) {
        #pragma unroll
        for (int j = 0; j < OCG / 2; ++j) {
            const int oc0 = og * OCG + 2 * j;
            float*       op0 = out  + ((size_t)(b * COUT + oc0) * HO + ho) * WO;
            float*       op1 = op0 + (size_t)HO * WO;
            const float* bp0 = bias + ((size_t)oc0 * HO + ho) * WO;
            const float* bp1 = bp0 + (size_t)HO * WO;
            #pragma unroll
            for (int p = 0; p < 8; ++p) {
                int wo = w0 + tx8 + p;
                if (wo < WO) {
                    float2 v = unpack2(accp[j][p]);
                    op0[wo] = v.x + bp0[wo];
                    op1[wo] = v.y + bp1[wo];
                }
            }
        }
    }
}

// ---------------------------------------------------------------------------
extern "C" void kernel_launch(void* const* d_in, const int* in_sizes, int n_in,
                              void* d_out, int out_size) {
    const float* x       = (const float*)d_in[0];
    const float* weights = (const float*)d_in[1];
    const float* bias    = (const float*)d_in[2];
    const int*   cn      = (const int*)d_in[3];
    float* out = (float*)d_out;

    build_kdense<<<COUT, CIN * 9>>>(weights, cn);

    dim3 grid(8, COUT / OCG, B);
    conv_kernel<<<grid, 256>>>(x, bias, out);
}

// round 7
// speedup vs baseline: 1.5375x; 1.0166x over previous
#include <cuda_runtime.h>
#include <cuda_bf16.h>
#include <cstdint>

// Problem dims
#define B    32
#define CIN  32
#define COUT 64
#define HH   128
#define WW   128
#define MAXCN 64
#define HO   126
#define WO   126

// Effective dense kernel scratch: [COUT][CIN][9]
__device__ float g_kd[COUT * CIN * 9];

// ---------------------------------------------------------------------------
// Kernel 1: fold padded kernel bank into dense [O, C, 3, 3]
// ---------------------------------------------------------------------------
__global__ void build_kdense(const float* __restrict__ w,
                             const int* __restrict__ cn) {
    int o = blockIdx.x;
    int t = threadIdx.x;
    if (t < CIN * 9) {
        int c = t / 9;
        int k = t % 9;
        int cnum = cn[o];
        float v = 0.f;
        if (c < cnum)        v += w[(o * MAXCN + c) * 9 + k];
        if (c + CIN < cnum)  v += w[(o * MAXCN + c + CIN) * 9 + k];
        g_kd[o * (CIN * 9) + t] = v;
    }
}

// ---------------------------------------------------------------------------
// Packed f32x2 + cp.async helpers
// ---------------------------------------------------------------------------
__device__ __forceinline__ void ffma2(unsigned long long& d,
                                      unsigned long long a,
                                      unsigned long long b) {
    asm("fma.rn.f32x2 %0, %1, %2, %0;" : "+l"(d) : "l"(a), "l"(b));
}
__device__ __forceinline__ unsigned long long pack2(float x, float y) {
    unsigned long long r;
    asm("mov.b64 %0, {%1, %2};" : "=l"(r) : "f"(x), "f"(y));
    return r;
}
__device__ __forceinline__ float2 unpack2(unsigned long long v) {
    float2 f;
    asm("mov.b64 {%0, %1}, %2;" : "=f"(f.x), "=f"(f.y) : "l"(v));
    return f;
}
__device__ __forceinline__ void cp_async4(uint32_t saddr, const float* gptr,
                                          int goff) {
    asm volatile(
        "{\n\t"
        ".reg .pred p;\n\t"
        "setp.ge.s32 p, %2, 0;\n\t"
        "@p cp.async.ca.shared.global [%0], [%1], 4;\n\t"
        "}" :: "r"(saddr), "l"(gptr), "r"(goff));
}
__device__ __forceinline__ void cp_commit() {
    asm volatile("cp.async.commit_group;");
}
__device__ __forceinline__ void cp_wait_all() {
    asm volatile("cp.async.wait_group 0;");
}

// ---------------------------------------------------------------------------
// Kernel 2: direct conv, FFMA2, cp.async double-buffer.
// Tile: 32 rows x 32 cols x 8 oc. Thread: ty=tid/8 (row), 4 px at tx4.
// Small acc footprint (32 u64-reg pairs) -> register slack -> batched LDS.
// ---------------------------------------------------------------------------
#define TH 32
#define TW 32
#define OCG 8
#define XT_H 34
#define XT_W 36              // padded from 34: rows 16B-aligned
#define XT_N (XT_H * XT_W)   // 1224
#define LDS_PT 5             // ceil(1224/256)

__global__ __launch_bounds__(256, 2)
void conv_kernel(const float* __restrict__ x,
                 const float* __restrict__ bias,
                 float* __restrict__ out) {
    __shared__ float  xs[2][XT_N];          // 2 * 4896 B
    __shared__ float2 ws2[CIN][9][OCG/2];   // 9216 B

    const int tid = threadIdx.x;
    const int ty  = tid >> 3;               // 0..31
    const int tx4 = (tid & 7) * 4;          // 0..28

    const int tilew = blockIdx.x & 3;       // 4 x 4 tiles cover 126x126
    const int tileh = blockIdx.x >> 2;
    const int og    = blockIdx.y;           // 0..7
    const int b     = blockIdx.z;

    const int h0 = tileh * TH;
    const int w0 = tilew * TW;

    // Pack weights as oc-pairs: ws2[c][k][j] = (kd[og*8+2j], kd[og*8+2j+1])
    for (int i = tid; i < CIN * 9 * (OCG / 2); i += 256) {
        int c = i / 36;
        int k = (i % 36) >> 2;
        int j = i & 3;
        int oc0 = og * OCG + 2 * j;
        ws2[c][k][j] = make_float2(g_kd[oc0 * (CIN * 9) + c * 9 + k],
                                   g_kd[(oc0 + 1) * (CIN * 9) + c * 9 + k]);
    }

    // Gather offsets (constant across channels)
    int      goff[LDS_PT];
    uint32_t sa0[LDS_PT];
    #pragma unroll
    for (int k = 0; k < LDS_PT; ++k) {
        int i = tid + k * 256;
        bool sv = (i < XT_N);
        int r   = i / XT_W;
        int col = i % XT_W;
        int gr = h0 + r;
        int gc = w0 + col;
        bool gv = sv && (gr < HH) && (gc < WW) && (col < XT_H);
        goff[k] = gv ? (gr * WW + gc) : -1;
        sa0[k]  = (uint32_t)__cvta_generic_to_shared(&xs[0][sv ? i : 0]);
        if (sv && !gv) { xs[0][i] = 0.f; xs[1][i] = 0.f; }  // zero halo once
    }

    unsigned long long accp[OCG / 2][4];
    #pragma unroll
    for (int j = 0; j < OCG / 2; ++j)
        #pragma unroll
        for (int p = 0; p < 4; ++p) accp[j][p] = 0ull;

    const float* xb = x + (size_t)b * CIN * HH * WW;
    const uint32_t BUF_STRIDE = XT_N * 4;

    // Prologue: channel 0 into buffer 0
    #pragma unroll
    for (int k = 0; k < LDS_PT; ++k)
        cp_async4(sa0[k], xb + goff[k], goff[k]);
    cp_commit();
    cp_wait_all();
    __syncthreads();

    #pragma unroll 2
    for (int c = 0; c < CIN; ++c) {
        const int cur = c & 1;

        // Kick off next channel's async copy into the other buffer
        if (c + 1 < CIN) {
            const float* xc = xb + (size_t)(c + 1) * HH * WW;
            const uint32_t off = (cur ^ 1) ? BUF_STRIDE : 0u;
            #pragma unroll
            for (int k = 0; k < LDS_PT; ++k)
                cp_async4(sa0[k] + off, xc + goff[k], goff[k]);
            cp_commit();
        }

        // Compute from current buffer
        const float* xsb = xs[cur];
        #pragma unroll
        for (int kh = 0; kh < 3; ++kh) {
            // Batch all loads for this kh up front (register slack allows MLP)
            unsigned long long wv[3][OCG / 2];
            #pragma unroll
            for (int kw = 0; kw < 3; ++kw)
                #pragma unroll
                for (int j = 0; j < OCG / 2; ++j)
                    wv[kw][j] = *reinterpret_cast<const unsigned long long*>(
                        &ws2[c][kh * 3 + kw][j]);

            const float* row = xsb + (ty + kh) * XT_W + tx4;
            float4 a  = *(const float4*)(row);
            float2 b2 = *(const float2*)(row + 4);

            unsigned long long xx[6];
            xx[0] = pack2(a.x, a.x);   xx[1] = pack2(a.y, a.y);
            xx[2] = pack2(a.z, a.z);   xx[3] = pack2(a.w, a.w);
            xx[4] = pack2(b2.x, b2.x); xx[5] = pack2(b2.y, b2.y);

            #pragma unroll
            for (int kw = 0; kw < 3; ++kw)
                #pragma unroll
                for (int j = 0; j < OCG / 2; ++j)
                    #pragma unroll
                    for (int p = 0; p < 4; ++p)
                        ffma2(accp[j][p], wv[kw][j], xx[kw + p]);
        }

        cp_wait_all();
        __syncthreads();
    }

    // Epilogue: unpack, add bias, store
    const int ho = h0 + ty;
    if (ho < HO) {
        #pragma unroll
        for (int j = 0; j < OCG / 2; ++j) {
            const int oc0 = og * OCG + 2 * j;
            float*       op0 = out  + ((size_t)(b * COUT + oc0) * HO + ho) * WO;
            float*       op1 = op0 + (size_t)HO * WO;
            const float* bp0 = bias + ((size_t)oc0 * HO + ho) * WO;
            const float* bp1 = bp0 + (size_t)HO * WO;
            #pragma unroll
            for (int p = 0; p < 4; ++p) {
                int wo = w0 + tx4 + p;
                if (wo < WO) {
                    float2 v = unpack2(accp[j][p]);
                    op0[wo] = v.x + bp0[wo];
                    op1[wo] = v.y + bp1[wo];
                }
            }
        }
    }
}

// ---------------------------------------------------------------------------
extern "C" void kernel_launch(void* const* d_in, const int* in_sizes, int n_in,
                              void* d_out, int out_size) {
    const float* x       = (const float*)d_in[0];
    const float* weights = (const float*)d_in[1];
    const float* bias    = (const float*)d_in[2];
    const int*   cn      = (const int*)d_in[3];
    float* out = (float*)d_out;

    build_kdense<<<COUT, CIN * 9>>>(weights, cn);

    dim3 grid(16 /* 4x4 tiles */, COUT / OCG, B);
    conv_kernel<<<grid, 256>>>(x, bias, out);
}

// round 9
// speedup vs baseline: 1.5404x; 1.0019x over previous
#include <cuda_runtime.h>
#include <cuda_bf16.h>
#include <cstdint>

// ---------------------------------------------------------------------------
// Problem dims
// ---------------------------------------------------------------------------
#define BB    32
#define CIN   32
#define COUT  64
#define HH    128
#define WW    128
#define MAXCN 64
#define HO    126
#define WO    126
#define NPIX  (HO * WO)          // 15876
#define KTOT  (CIN * 9)          // 288
#define TILE_M 128
#define NT_PER_B ((NPIX + TILE_M - 1) / TILE_M)   // 125
#define NTILES (BB * NT_PER_B)                    // 4000
#define CH_PER_CHUNK 8
#define KCHUNK (CH_PER_CHUNK * 9)                 // 72
#define NCHUNK 4

#define WS_STRIDE 292     // floats per oc row (64 x 292 x 4 = 74752 B)
#define AS_STRIDE 76      // floats per px row (128 x 76 x 4 = 38912 B)
#define OFF_WS 0
#define OFF_AS (COUT * WS_STRIDE)                    // 18688 floats
#define OFF_PX (OFF_AS + TILE_M * AS_STRIDE)         // 28416 floats
#define SMEM_FLOATS (OFF_PX + TILE_M)
#define SMEM_TOTAL (SMEM_FLOATS * 4)                 // 114688 B

// Effective dense kernel scratch: [COUT][KTOT], k = c*9 + tap
__device__ float g_kd[COUT * KTOT];

// ---------------------------------------------------------------------------
// Kernel 1: fold padded kernel bank into dense [O, C*9]
// ---------------------------------------------------------------------------
__global__ void build_kdense(const float* __restrict__ w,
                             const int* __restrict__ cn) {
    int o = blockIdx.x;
    int t = threadIdx.x;
    if (t < KTOT) {
        int c = t / 9;
        int k = t % 9;
        int cnum = cn[o];
        float v = 0.f;
        if (c < cnum)        v += w[(o * MAXCN + c) * 9 + k];
        if (c + CIN < cnum)  v += w[(o * MAXCN + c + CIN) * 9 + k];
        g_kd[o * KTOT + t] = v;
    }
}

// ---------------------------------------------------------------------------
// tf32 helpers
// ---------------------------------------------------------------------------
__device__ __forceinline__ float to_tf32(float v) {
    uint32_t r;
    asm("cvt.rna.tf32.f32 %0, %1;" : "=r"(r) : "f"(v));
    return __uint_as_float(r);
}
// D += A(16x8) * B(8x8), tf32 inputs, f32 accum.
// A frag (4): a0(g,t) a1(g+8,t) a2(g,t+4) a3(g+8,t+4)   [g=lane/4, t=lane%4]
// B frag (2): b0(k=t, n=g) b1(k=t+4, n=g)
// C frag (4): c0(g,2t) c1(g,2t+1) c2(g+8,2t) c3(g+8,2t+1)
__device__ __forceinline__ void mma_tf32(float c[4], const uint32_t a[4],
                                         const uint32_t b[2]) {
    asm volatile(
        "mma.sync.aligned.m16n8k8.row.col.f32.tf32.tf32.f32 "
        "{%0,%1,%2,%3}, {%4,%5,%6,%7}, {%8,%9}, {%0,%1,%2,%3};"
        : "+f"(c[0]), "+f"(c[1]), "+f"(c[2]), "+f"(c[3])
        : "r"(a[0]), "r"(a[1]), "r"(a[2]), "r"(a[3]),
          "r"(b[0]), "r"(b[1]));
}

// ---------------------------------------------------------------------------
// Kernel 2: persistent tf32 implicit-GEMM conv via mma.sync.
// CTA tile: 128 output pixels x 64 output channels, K=288 in 4 chunks of 72.
// 512 threads = 16 warps: warp (mr = w&7) owns rows mr*16..+15,
//                         (nc = w>>3) owns cols nc*32..+31 (4 n8 blocks).
// ---------------------------------------------------------------------------
__global__ __launch_bounds__(512, 1)
void conv_mma(const float* __restrict__ x,
              const float* __restrict__ bias,
              float* __restrict__ out) {
    extern __shared__ float sm[];
    float* Ws = sm + OFF_WS;
    float* As = sm + OFF_AS;
    int*   px = (int*)(sm + OFF_PX);

    const int tid = threadIdx.x;
    const int wid = tid >> 5;
    const int lid = tid & 31;
    const int gid = lid >> 2;     // groupID 0..7
    const int tig = lid & 3;      // thread-in-group 0..3
    const int mr  = wid & 7;      // M strip (16 rows)
    const int nc  = wid >> 3;     // N half (32 cols)

    // Stage weights once (persistent CTA): Ws[o][k] = tf32(g_kd[o][k])
    for (int i = tid; i < COUT * KTOT; i += 512) {
        int o = i / KTOT, k = i - o * KTOT;
        Ws[o * WS_STRIDE + k] = to_tf32(g_kd[i]);
    }
    __syncthreads();

    for (int T = blockIdx.x; T < NTILES; T += gridDim.x) {
        const int b     = T / NT_PER_B;
        const int tbase = (T % NT_PER_B) * TILE_M;

        // Pixel map for this tile (OOB tail rows clamped; never stored)
        if (tid < TILE_M) {
            int p  = tbase + tid;
            int pp = (p < NPIX) ? p : 0;
            int ho = pp / WO;
            int wo = pp - ho * WO;
            px[tid] = ho * WW + wo;
        }
        __syncthreads();

        float acc[4][4];
        #pragma unroll
        for (int n = 0; n < 4; ++n)
            #pragma unroll
            for (int q = 0; q < 4; ++q) acc[n][q] = 0.f;

        const float* xb = x + (size_t)b * CIN * HH * WW;

        for (int g = 0; g < NCHUNK; ++g) {
            // --- im2col build: channels [8g,8g+8), 9 taps, 128 pixels ---
            for (int i = tid; i < CH_PER_CHUNK * 3 * TILE_M; i += 512) {
                int cl  = i / (3 * TILE_M);
                int rem = i - cl * 3 * TILE_M;
                int kh  = rem >> 7;
                int r   = rem & 127;
                const float* gp = xb +
                    (size_t)(g * CH_PER_CHUNK + cl) * HH * WW + px[r] + kh * WW;
                float v0 = __ldg(gp);
                float v1 = __ldg(gp + 1);
                float v2 = __ldg(gp + 2);
                float* ar = As + r * AS_STRIDE + cl * 9 + kh * 3;
                ar[0] = to_tf32(v0);
                ar[1] = to_tf32(v1);
                ar[2] = to_tf32(v2);
            }
            __syncthreads();

            // --- mma phase: 9 K-steps of 8 ---
            const float* arow0 = As + (mr * 16 + gid) * AS_STRIDE;       // row g
            const float* arow1 = arow0 + 8 * AS_STRIDE;                  // row g+8
            const int kgbase = g * KCHUNK;
            #pragma unroll
            for (int ks = 0; ks < 9; ++ks) {
                const int k0 = ks * 8;
                uint32_t a[4];
                a[0] = __float_as_uint(arow0[k0 + tig]);
                a[1] = __float_as_uint(arow1[k0 + tig]);
                a[2] = __float_as_uint(arow0[k0 + tig + 4]);
                a[3] = __float_as_uint(arow1[k0 + tig + 4]);
                #pragma unroll
                for (int nblk = 0; nblk < 4; ++nblk) {
                    const int n0 = nc * 32 + nblk * 8;
                    const float* wr = Ws + (n0 + gid) * WS_STRIDE + kgbase + k0;
                    uint32_t bfr[2];
                    bfr[0] = __float_as_uint(wr[tig]);
                    bfr[1] = __float_as_uint(wr[tig + 4]);
                    mma_tf32(acc[nblk], a, bfr);
                }
            }
            __syncthreads();   // all reads of As done before next build
        }

        // --- epilogue: scatter C frags + bias ---
        const int row0 = mr * 16 + gid;
        const int row1 = row0 + 8;
        const int p0 = tbase + row0;
        const int p1 = tbase + row1;
        #pragma unroll
        for (int nblk = 0; nblk < 4; ++nblk) {
            const int col0 = nc * 32 + nblk * 8 + 2 * tig;
            const size_t ob0 = ((size_t)b * COUT + col0) * NPIX;
            const size_t bb0 = (size_t)col0 * NPIX;
            if (p0 < NPIX) {
                out[ob0 + p0]        = acc[nblk][0] + bias[bb0 + p0];
                out[ob0 + NPIX + p0] = acc[nblk][1] + bias[bb0 + NPIX + p0];
            }
            if (p1 < NPIX) {
                out[ob0 + p1]        = acc[nblk][2] + bias[bb0 + p1];
                out[ob0 + NPIX + p1] = acc[nblk][3] + bias[bb0 + NPIX + p1];
            }
        }
        // px/As rewritten next iteration only after the __syncthreads that
        // follows its build; epilogue touches no smem.
        __syncthreads();
    }
}

// ---------------------------------------------------------------------------
extern "C" void kernel_launch(void* const* d_in, const int* in_sizes, int n_in,
                              void* d_out, int out_size) {
    const float* x       = (const float*)d_in[0];  // [32,32,128,128]
    const float* weights = (const float*)d_in[1];  // [64,64,3,3]
    const float* bias    = (const float*)d_in[2];  // [64,126,126]
    const int*   cn      = (const int*)d_in[3];    // [64]
    float* out = (float*)d_out;                    // [32,64,126,126]

    static bool attr_set = false;
    if (!attr_set) {
        cudaFuncSetAttribute(conv_mma,
                             cudaFuncAttributeMaxDynamicSharedMemorySize,
                             SMEM_TOTAL);
        attr_set = true;
    }

    build_kdense<<<COUT, KTOT>>>(weights, cn);
    conv_mma<<<148, 512, SMEM_TOTAL>>>(x, bias, out);
}

// round 10
// speedup vs baseline: 2.3762x; 1.5425x over previous
#include <cuda_runtime.h>
#include <cuda_bf16.h>
#include <cstdint>

// ---------------------------------------------------------------------------
// Problem dims
// ---------------------------------------------------------------------------
#define BB    32
#define CIN   32
#define COUT  64
#define HH    128
#define WW    128
#define MAXCN 64
#define HO    126
#define WO    126
#define NPIX  (HO * WO)          // 15876
#define KTOT  (CIN * 9)          // 288
#define TILE_M 128
#define NT_PER_B ((NPIX + TILE_M - 1) / TILE_M)   // 125
#define NTILES (BB * NT_PER_B)                    // 4000
#define CH_PER_CHUNK 8
#define KCHUNK (CH_PER_CHUNK * 9)                 // 72
#define NCHUNK 4

#define WS_STRIDE 292     // floats per oc row  (conflict-free B frag loads)
#define AS_STRIDE 76      // floats per px row  (conflict-free A frag loads)
#define OFF_WS 0
#define OFF_AS (COUT * WS_STRIDE)                       // 18688 floats
#define AS_BUF_FLOATS (TILE_M * AS_STRIDE)              // 9728
#define OFF_PX (OFF_AS + 2 * AS_BUF_FLOATS)             // double-buffered As
#define SMEM_FLOATS (OFF_PX + TILE_M)
#define SMEM_TOTAL (SMEM_FLOATS * 4)                    // 153088 B

// Effective dense kernel scratch: [COUT][KTOT], k = c*9 + tap
__device__ float g_kd[COUT * KTOT];

// ---------------------------------------------------------------------------
// Kernel 1: fold padded kernel bank into dense [O, C*9]
// ---------------------------------------------------------------------------
__global__ void build_kdense(const float* __restrict__ w,
                             const int* __restrict__ cn) {
    int o = blockIdx.x;
    int t = threadIdx.x;
    if (t < KTOT) {
        int c = t / 9;
        int k = t % 9;
        int cnum = cn[o];
        float v = 0.f;
        if (c < cnum)        v += w[(o * MAXCN + c) * 9 + k];
        if (c + CIN < cnum)  v += w[(o * MAXCN + c + CIN) * 9 + k];
        g_kd[o * KTOT + t] = v;
    }
}

// ---------------------------------------------------------------------------
// helpers
// ---------------------------------------------------------------------------
__device__ __forceinline__ float to_tf32(float v) {
    uint32_t r;
    asm("cvt.rna.tf32.f32 %0, %1;" : "=r"(r) : "f"(v));
    return __uint_as_float(r);
}
__device__ __forceinline__ uint32_t cvt_rna_u32(float v) {
    uint32_t r;
    asm("cvt.rna.tf32.f32 %0, %1;" : "=r"(r) : "f"(v));
    return r;
}
__device__ __forceinline__ void cp_async4(uint32_t saddr, const float* gptr) {
    asm volatile("cp.async.ca.shared.global [%0], [%1], 4;"
                 :: "r"(saddr), "l"(gptr));
}
__device__ __forceinline__ void cp_commit() {
    asm volatile("cp.async.commit_group;");
}
template <int N>
__device__ __forceinline__ void cp_wait() {
    asm volatile("cp.async.wait_group %0;" :: "n"(N));
}
// D += A(16x8) * B(8x8), tf32 in, f32 accum (fragment layout verified R9)
__device__ __forceinline__ void mma_tf32(float c[4], const uint32_t a[4],
                                         const uint32_t b[2]) {
    asm volatile(
        "mma.sync.aligned.m16n8k8.row.col.f32.tf32.tf32.f32 "
        "{%0,%1,%2,%3}, {%4,%5,%6,%7}, {%8,%9}, {%0,%1,%2,%3};"
        : "+f"(c[0]), "+f"(c[1]), "+f"(c[2]), "+f"(c[3])
        : "r"(a[0]), "r"(a[1]), "r"(a[2]), "r"(a[3]),
          "r"(b[0]), "r"(b[1]));
}

// ---------------------------------------------------------------------------
// Kernel 2: persistent tf32 implicit-GEMM, cp.async double-buffered im2col.
// CTA tile: 128 px x 64 oc, K=288 in 4 chunks of 72.
// 512 thr = 16 warps: warp(mr=w&7) rows mr*16..+15, (nc=w>>3) cols nc*32..+31.
// ---------------------------------------------------------------------------
__global__ __launch_bounds__(512, 1)
void conv_mma(const float* __restrict__ x,
              const float* __restrict__ bias,
              float* __restrict__ out) {
    extern __shared__ float sm[];
    float* Ws = sm + OFF_WS;
    int*   px = (int*)(sm + OFF_PX);

    const int tid = threadIdx.x;
    const int wid = tid >> 5;
    const int lid = tid & 31;
    const int gid = lid >> 2;
    const int tig = lid & 3;
    const int mr  = wid & 7;
    const int nc  = wid >> 3;

    // Stage tf32 weights once per persistent CTA
    for (int i = tid; i < COUT * KTOT; i += 512) {
        int o = i / KTOT, k = i - o * KTOT;
        Ws[o * WS_STRIDE + k] = to_tf32(g_kd[i]);
    }

    // Per-thread copy slots: 6 groups of (r, cl, kh), 3 kw each = 18 elems/chunk
    int gsub[6];      // px-table index r
    int coff[6];      // cl*HH*WW + kh*WW  (channel-local part added later)
    uint32_t sdst[6]; // smem dst base (buffer 0) for the 3-float run
    #pragma unroll
    for (int q = 0; q < 6; ++q) {
        int i   = tid + q * 512;                // < 3072 = 8*3*128
        int cl  = i / (3 * TILE_M);
        int rem = i - cl * 3 * TILE_M;
        int kh  = rem >> 7;
        int r   = rem & 127;
        gsub[q] = r;
        coff[q] = cl * HH * WW + kh * WW;
        sdst[q] = (uint32_t)__cvta_generic_to_shared(
            sm + OFF_AS + r * AS_STRIDE + cl * 9 + kh * 3);
    }
    const uint32_t ABUF = AS_BUF_FLOATS * 4;    // byte stride between buffers
    __syncthreads();

    for (int T = blockIdx.x; T < NTILES; T += gridDim.x) {
        const int b     = T / NT_PER_B;
        const int tbase = (T % NT_PER_B) * TILE_M;
        const float* xb = x + (size_t)b * CIN * HH * WW;

        if (tid < TILE_M) {
            int p  = tbase + tid;
            int pp = (p < NPIX) ? p : 0;
            int ho = pp / WO;
            px[tid] = ho * WW + (pp - ho * WO);
        }
        __syncthreads();

        // Prologue: async-copy chunk 0 into buffer 0
        #pragma unroll
        for (int q = 0; q < 6; ++q) {
            const float* gp = xb + coff[q] + px[gsub[q]];
            uint32_t sa = sdst[q];
            cp_async4(sa,     gp);
            cp_async4(sa + 4, gp + 1);
            cp_async4(sa + 8, gp + 2);
        }
        cp_commit();

        float acc[4][4];
        #pragma unroll
        for (int n = 0; n < 4; ++n)
            #pragma unroll
            for (int q2 = 0; q2 < 4; ++q2) acc[n][q2] = 0.f;

        #pragma unroll
        for (int g = 0; g < NCHUNK; ++g) {
            // Prefetch chunk g+1 into the other buffer (overlaps mma below)
            if (g + 1 < NCHUNK) {
                const float* xc = xb + (size_t)(g + 1) * CH_PER_CHUNK * HH * WW;
                const uint32_t off = ((g + 1) & 1) ? ABUF : 0u;
                #pragma unroll
                for (int q = 0; q < 6; ++q) {
                    const float* gp = xc + coff[q] + px[gsub[q]];
                    uint32_t sa = sdst[q] + off;
                    cp_async4(sa,     gp);
                    cp_async4(sa + 4, gp + 1);
                    cp_async4(sa + 8, gp + 2);
                }
                cp_commit();
                cp_wait<1>();      // chunk g landed
            } else {
                cp_wait<0>();
            }
            __syncthreads();

            // --- mma phase on buffer g&1 (raw fp32; cvt.rna at fragment) ---
            const float* As = sm + OFF_AS + (g & 1) * AS_BUF_FLOATS;
            const float* arow0 = As + (mr * 16 + gid) * AS_STRIDE;
            const float* arow1 = arow0 + 8 * AS_STRIDE;
            const int kgbase = g * KCHUNK;
            #pragma unroll
            for (int ks = 0; ks < 9; ++ks) {
                const int k0 = ks * 8;
                uint32_t a[4];
                a[0] = cvt_rna_u32(arow0[k0 + tig]);
                a[1] = cvt_rna_u32(arow1[k0 + tig]);
                a[2] = cvt_rna_u32(arow0[k0 + tig + 4]);
                a[3] = cvt_rna_u32(arow1[k0 + tig + 4]);
                #pragma unroll
                for (int nblk = 0; nblk < 4; ++nblk) {
                    const int n0 = nc * 32 + nblk * 8;
                    const float* wr = Ws + (n0 + gid) * WS_STRIDE + kgbase + k0;
                    uint32_t bfr[2];
                    bfr[0] = __float_as_uint(wr[tig]);
                    bfr[1] = __float_as_uint(wr[tig + 4]);
                    mma_tf32(acc[nblk], a, bfr);
                }
            }
            __syncthreads();   // buffer g&1 free for the g+2 prefetch
        }

        // --- epilogue: scatter C frags + bias ---
        const int row0 = mr * 16 + gid;
        const int row1 = row0 + 8;
        const int p0 = tbase + row0;
        const int p1 = tbase + row1;
        #pragma unroll
        for (int nblk = 0; nblk < 4; ++nblk) {
            const int col0 = nc * 32 + nblk * 8 + 2 * tig;
            const size_t ob0 = ((size_t)b * COUT + col0) * NPIX;
            const size_t bb0 = (size_t)col0 * NPIX;
            if (p0 < NPIX) {
                out[ob0 + p0]        = acc[nblk][0] + bias[bb0 + p0];
                out[ob0 + NPIX + p0] = acc[nblk][1] + bias[bb0 + NPIX + p0];
            }
            if (p1 < NPIX) {
                out[ob0 + p1]        = acc[nblk][2] + bias[bb0 + p1];
                out[ob0 + NPIX + p1] = acc[nblk][3] + bias[bb0 + NPIX + p1];
            }
        }
        __syncthreads();   // px rewrite next tile
    }
}

// ---------------------------------------------------------------------------
extern "C" void kernel_launch(void* const* d_in, const int* in_sizes, int n_in,
                              void* d_out, int out_size) {
    const float* x       = (const float*)d_in[0];  // [32,32,128,128]
    const float* weights = (const float*)d_in[1];  // [64,64,3,3]
    const float* bias    = (const float*)d_in[2];  // [64,126,126]
    const int*   cn      = (const int*)d_in[3];    // [64]
    float* out = (float*)d_out;                    // [32,64,126,126]

    static bool attr_set = false;
    if (!attr_set) {
        cudaFuncSetAttribute(conv_mma,
                             cudaFuncAttributeMaxDynamicSharedMemorySize,
                             SMEM_TOTAL);
        attr_set = true;
    }

    build_kdense<<<COUT, KTOT>>>(weights, cn);
    conv_mma<<<148, 512, SMEM_TOTAL>>>(x, bias, out);
}